// round 3
// baseline (speedup 1.0000x reference)
#include <cuda_runtime.h>

#define NROWS 100000
#define DIM 256
#define EPS 1e-6f

#define BM 128
#define BN 128
#define BK 8
#define TM 8
#define TN 8
#define KV_CHUNK 512

// Scratch (allocation-guard-safe __device__ globals)
__device__ float g_Q[NROWS * DIM];
__device__ float g_K[NROWS * DIM];
__device__ float g_V[NROWS * DIM];
__device__ float g_KV[DIM * DIM];
__device__ float g_ksum[DIM];
__device__ float g_norm[NROWS];

// ---------------------------------------------------------------------------
// init: zero the accumulators (must run every graph replay)
// ---------------------------------------------------------------------------
__global__ void init_kernel() {
    int t = blockIdx.x * blockDim.x + threadIdx.x;
    if (t < DIM * DIM) g_KV[t] = 0.0f;
    if (t < DIM)       g_ksum[t] = 0.0f;
}

// ---------------------------------------------------------------------------
// qkv: Q=relu(xWq+bq), K=relu(xWk+bk), V=xWv+bv  (one fused launch)
// grid: (6, 782)  x = matrix*2 + colhalf, y = row tile
// Also accumulates ksum (post-relu column sums of K) via smem reduce + atomics.
// ---------------------------------------------------------------------------
__global__ __launch_bounds__(256, 2) void qkv_kernel(
    const float* __restrict__ x,
    const float* __restrict__ Wq, const float* __restrict__ bq,
    const float* __restrict__ Wk, const float* __restrict__ bk,
    const float* __restrict__ Wv, const float* __restrict__ bv)
{
    const int zy   = blockIdx.x;          // 0..5
    const int z    = zy >> 1;             // 0:Q 1:K 2:V
    const int col0 = (zy & 1) * BN;
    const int row0 = blockIdx.y * BM;

    const float* B; const float* bias; float* C;
    if (z == 0)      { B = Wq; bias = bq; C = g_Q; }
    else if (z == 1) { B = Wk; bias = bk; C = g_K; }
    else             { B = Wv; bias = bv; C = g_V; }
    const bool relu = (z < 2);

    __shared__ float smem[2 * BK * BM];   // 2048 floats
    float* As = smem;                     // [BK][BM] (transposed x tile)
    float* Bs = smem + BK * BM;           // [BK][BN]

    const int t = threadIdx.x;
    const int aRow = t >> 1, aCol = (t & 1) << 2;
    const int bRow = t >> 5, bCol = (t & 31) << 2;
    const int ty = t >> 4, tx = t & 15;

    float acc[TM][TN];
#pragma unroll
    for (int i = 0; i < TM; i++)
#pragma unroll
        for (int j = 0; j < TN; j++) acc[i][j] = 0.0f;

    for (int k0 = 0; k0 < DIM; k0 += BK) {
        float4 av = make_float4(0.f, 0.f, 0.f, 0.f);
        const int gr = row0 + aRow;
        if (gr < NROWS) av = *(const float4*)&x[gr * DIM + k0 + aCol];
        As[(aCol + 0) * BM + aRow] = av.x;
        As[(aCol + 1) * BM + aRow] = av.y;
        As[(aCol + 2) * BM + aRow] = av.z;
        As[(aCol + 3) * BM + aRow] = av.w;

        const float4 bv4 = *(const float4*)&B[(k0 + bRow) * DIM + col0 + bCol];
        *(float4*)&Bs[bRow * BN + bCol] = bv4;
        __syncthreads();

#pragma unroll
        for (int kk = 0; kk < BK; kk++) {
            float a[TM], b[TN];
#pragma unroll
            for (int i = 0; i < TM; i++) a[i] = As[kk * BM + ty * TM + i];
#pragma unroll
            for (int j = 0; j < TN; j++) b[j] = Bs[kk * BN + tx * TN + j];
#pragma unroll
            for (int i = 0; i < TM; i++)
#pragma unroll
                for (int j = 0; j < TN; j++) acc[i][j] += a[i] * b[j];
        }
        __syncthreads();
    }

    // epilogue: bias (+relu), store, accumulate K column sums
    float bvv[TN];
#pragma unroll
    for (int j = 0; j < TN; j++) bvv[j] = bias[col0 + tx * TN + j];

    float colsum[TN];
#pragma unroll
    for (int j = 0; j < TN; j++) colsum[j] = 0.0f;

#pragma unroll
    for (int i = 0; i < TM; i++) {
        const int gr = row0 + ty * TM + i;
        float v[TN];
#pragma unroll
        for (int j = 0; j < TN; j++) {
            v[j] = acc[i][j] + bvv[j];
            if (relu) v[j] = fmaxf(v[j], 0.0f);
        }
        if (gr < NROWS) {
#pragma unroll
            for (int j = 0; j < TN; j++) colsum[j] += v[j];
            *(float4*)&C[gr * DIM + col0 + tx * TN]     = make_float4(v[0], v[1], v[2], v[3]);
            *(float4*)&C[gr * DIM + col0 + tx * TN + 4] = make_float4(v[4], v[5], v[6], v[7]);
        }
    }

    if (z == 1) {   // ksum for K blocks only
        __syncthreads();
#pragma unroll
        for (int j = 0; j < TN; j++) smem[ty * BN + tx * TN + j] = colsum[j];
        __syncthreads();
        if (t < BN) {
            float s = 0.0f;
#pragma unroll
            for (int r = 0; r < 16; r++) s += smem[r * BN + t];
            atomicAdd(&g_ksum[col0 + t], s);
        }
    }
}

// ---------------------------------------------------------------------------
// kv: KV[d][e] += sum_n K[n][d] * V[n][e]  (split-k over row chunks)
// grid: (4, nchunks). x: bit0 = d tile, bit1 = e tile.
// ---------------------------------------------------------------------------
__global__ __launch_bounds__(256, 2) void kv_kernel() {
    const int d0 = (blockIdx.x & 1) * BM;
    const int e0 = (blockIdx.x >> 1) * BN;
    const int n0 = blockIdx.y * KV_CHUNK;
    const int n1 = min(n0 + KV_CHUNK, NROWS);

    __shared__ float smem[2 * BK * BM];
    float* Ks = smem;
    float* Vs = smem + BK * BM;

    const int t = threadIdx.x;
    const int lRow = t >> 5, lCol = (t & 31) << 2;
    const int ty = t >> 4, tx = t & 15;

    float acc[TM][TN];
#pragma unroll
    for (int i = 0; i < TM; i++)
#pragma unroll
        for (int j = 0; j < TN; j++) acc[i][j] = 0.0f;

    for (int n = n0; n < n1; n += BK) {
        const int gr = n + lRow;
        float4 kf = make_float4(0.f, 0.f, 0.f, 0.f);
        float4 vf = make_float4(0.f, 0.f, 0.f, 0.f);
        if (gr < n1) {
            kf = *(const float4*)&g_K[gr * DIM + d0 + lCol];
            vf = *(const float4*)&g_V[gr * DIM + e0 + lCol];
        }
        *(float4*)&Ks[lRow * BM + lCol] = kf;
        *(float4*)&Vs[lRow * BN + lCol] = vf;
        __syncthreads();

#pragma unroll
        for (int kk = 0; kk < BK; kk++) {
            float a[TM], b[TN];
#pragma unroll
            for (int i = 0; i < TM; i++) a[i] = Ks[kk * BM + ty * TM + i];
#pragma unroll
            for (int j = 0; j < TN; j++) b[j] = Vs[kk * BN + tx * TN + j];
#pragma unroll
            for (int i = 0; i < TM; i++)
#pragma unroll
                for (int j = 0; j < TN; j++) acc[i][j] += a[i] * b[j];
        }
        __syncthreads();
    }

#pragma unroll
    for (int i = 0; i < TM; i++)
#pragma unroll
        for (int j = 0; j < TN; j++)
            atomicAdd(&g_KV[(d0 + ty * TM + i) * DIM + e0 + tx * TN + j], acc[i][j]);
}

// ---------------------------------------------------------------------------
// norm: g_norm[n] = dot(Q[n], ksum) + EPS   (warp per row)
// ---------------------------------------------------------------------------
__global__ void norm_kernel() {
    __shared__ float ks[DIM];
    const int t = threadIdx.x;
    if (t < DIM) ks[t] = g_ksum[t];
    __syncthreads();

    const int lane = t & 31;
    const int gw = (blockIdx.x * blockDim.x + t) >> 5;
    const int nw = (gridDim.x * blockDim.x) >> 5;
    for (int row = gw; row < NROWS; row += nw) {
        const float* q = &g_Q[row * DIM];
        float s = 0.0f;
#pragma unroll
        for (int i = 0; i < 8; i++) s += q[lane + i * 32] * ks[lane + i * 32];
#pragma unroll
        for (int o = 16; o; o >>= 1) s += __shfl_xor_sync(0xffffffffu, s, o);
        if (lane == 0) g_norm[row] = s + EPS;
    }
}

// ---------------------------------------------------------------------------
// out: out = (Q @ KV) / norm      grid: (2, 782)
// ---------------------------------------------------------------------------
__global__ __launch_bounds__(256, 2) void out_kernel(float* __restrict__ out) {
    const int col0 = blockIdx.x * BN;
    const int row0 = blockIdx.y * BM;

    __shared__ float smem[2 * BK * BM];
    float* As = smem;
    float* Bs = smem + BK * BM;

    const int t = threadIdx.x;
    const int aRow = t >> 1, aCol = (t & 1) << 2;
    const int bRow = t >> 5, bCol = (t & 31) << 2;
    const int ty = t >> 4, tx = t & 15;

    float acc[TM][TN];
#pragma unroll
    for (int i = 0; i < TM; i++)
#pragma unroll
        for (int j = 0; j < TN; j++) acc[i][j] = 0.0f;

    for (int k0 = 0; k0 < DIM; k0 += BK) {
        float4 av = make_float4(0.f, 0.f, 0.f, 0.f);
        const int gr = row0 + aRow;
        if (gr < NROWS) av = *(const float4*)&g_Q[gr * DIM + k0 + aCol];
        As[(aCol + 0) * BM + aRow] = av.x;
        As[(aCol + 1) * BM + aRow] = av.y;
        As[(aCol + 2) * BM + aRow] = av.z;
        As[(aCol + 3) * BM + aRow] = av.w;

        const float4 bv4 = *(const float4*)&g_KV[(k0 + bRow) * DIM + col0 + bCol];
        *(float4*)&Bs[bRow * BN + bCol] = bv4;
        __syncthreads();

#pragma unroll
        for (int kk = 0; kk < BK; kk++) {
            float a[TM], b[TN];
#pragma unroll
            for (int i = 0; i < TM; i++) a[i] = As[kk * BM + ty * TM + i];
#pragma unroll
            for (int j = 0; j < TN; j++) b[j] = Bs[kk * BN + tx * TN + j];
#pragma unroll
            for (int i = 0; i < TM; i++)
#pragma unroll
                for (int j = 0; j < TN; j++) acc[i][j] += a[i] * b[j];
        }
        __syncthreads();
    }

#pragma unroll
    for (int i = 0; i < TM; i++) {
        const int gr = row0 + ty * TM + i;
        if (gr < NROWS) {
            const float inv = 1.0f / g_norm[gr];
            float v[TN];
#pragma unroll
            for (int j = 0; j < TN; j++) v[j] = acc[i][j] * inv;
            *(float4*)&out[gr * DIM + col0 + tx * TN]     = make_float4(v[0], v[1], v[2], v[3]);
            *(float4*)&out[gr * DIM + col0 + tx * TN + 4] = make_float4(v[4], v[5], v[6], v[7]);
        }
    }
}

// ---------------------------------------------------------------------------
extern "C" void kernel_launch(void* const* d_in, const int* in_sizes, int n_in,
                              void* d_out, int out_size) {
    const float* x  = (const float*)d_in[0];
    const float* Wq = (const float*)d_in[1];
    const float* bq = (const float*)d_in[2];
    const float* Wk = (const float*)d_in[3];
    const float* bk = (const float*)d_in[4];
    const float* Wv = (const float*)d_in[5];
    const float* bv = (const float*)d_in[6];
    float* out = (float*)d_out;

    const int rowTiles = (NROWS + BM - 1) / BM;           // 782
    const int nchunks  = (NROWS + KV_CHUNK - 1) / KV_CHUNK; // 196

    init_kernel<<<(DIM * DIM + 255) / 256, 256>>>();
    qkv_kernel<<<dim3(6, rowTiles), 256>>>(x, Wq, bq, Wk, bk, Wv, bv);
    kv_kernel<<<dim3(4, nchunks), 256>>>();
    norm_kernel<<<296, 256>>>();
    out_kernel<<<dim3(2, rowTiles), 256>>>(out);
}

// round 4
// speedup vs baseline: 2.8631x; 2.8631x over previous
#include <cuda_runtime.h>
#include <cstdint>

#define NROWS 100000
#define DIM 256
#define EPS 1e-6f

#define BM 128
#define BN 128
#define BKT 32          // k-tile depth
#define ASTRIDE 36      // A smem row stride (words) -> conflict-free fragments
#define BSTRIDE 136     // B smem row stride (words) -> conflict-free fragments
#define KV_CHUNKS 96
#define KV_CHUNK 1056   // 96*1056 = 101376 >= 100000, multiple of 32

// Scratch (allocation-guard-safe __device__ globals)
__device__ float g_Q[NROWS * DIM];
__device__ float g_K[NROWS * DIM];
__device__ float g_V[NROWS * DIM];
__device__ float g_KV[DIM * DIM];
__device__ float g_ksum[DIM];
__device__ float g_norm[NROWS];

__device__ __forceinline__ uint32_t f32_tf32(float f) {
    uint32_t r;
    asm("cvt.rna.tf32.f32 %0, %1;" : "=r"(r) : "f"(f));
    return r;
}

__device__ __forceinline__ void mma_tf32(float c[4], const uint32_t a[4],
                                         uint32_t b0, uint32_t b1) {
    asm volatile(
        "mma.sync.aligned.m16n8k8.row.col.f32.tf32.tf32.f32 "
        "{%0,%1,%2,%3},{%4,%5,%6,%7},{%8,%9},{%0,%1,%2,%3};\n"
        : "+f"(c[0]), "+f"(c[1]), "+f"(c[2]), "+f"(c[3])
        : "r"(a[0]), "r"(a[1]), "r"(a[2]), "r"(a[3]), "r"(b0), "r"(b1));
}

// ---------------------------------------------------------------------------
// init: zero the accumulators (must run every graph replay)
// ---------------------------------------------------------------------------
__global__ void init_kernel() {
    int t = blockIdx.x * blockDim.x + threadIdx.x;
    if (t < DIM * DIM) g_KV[t] = 0.0f;
    if (t < DIM)       g_ksum[t] = 0.0f;
}

// ---------------------------------------------------------------------------
// qkv: Q=relu(xWq+bq), K=relu(xWk+bk), V=xWv+bv   (tensor-core TF32)
// grid: (6, 782)  x = matrix*2 + colhalf (fastest -> x-tile L2 reuse), y = row tile
// ---------------------------------------------------------------------------
__global__ __launch_bounds__(256, 2) void qkv_kernel(
    const float* __restrict__ x,
    const float* __restrict__ Wq, const float* __restrict__ bq,
    const float* __restrict__ Wk, const float* __restrict__ bk,
    const float* __restrict__ Wv, const float* __restrict__ bv)
{
    const int zy   = blockIdx.x;
    const int z    = zy >> 1;             // 0:Q 1:K 2:V
    const int col0 = (zy & 1) * BN;
    const int row0 = blockIdx.y * BM;

    const float* B; const float* bias; float* C;
    if (z == 0)      { B = Wq; bias = bq; C = g_Q; }
    else if (z == 1) { B = Wk; bias = bk; C = g_K; }
    else             { B = Wv; bias = bv; C = g_V; }
    const bool relu = (z < 2);

    __shared__ uint32_t As[BM * ASTRIDE];   // [128 rows][32 k] stride 36
    __shared__ uint32_t Bs[BKT * BSTRIDE];  // [32 k][128 n]   stride 136

    const int t = threadIdx.x;
    const int l = t & 31;
    const int w = t >> 5;
    const int wm = w >> 1;                  // 0..3 -> 32-row warp tile
    const int wn = w & 1;                   // 0..1 -> 64-col warp tile

    float c[2][8][4];
#pragma unroll
    for (int mt = 0; mt < 2; mt++)
#pragma unroll
        for (int nt = 0; nt < 8; nt++)
#pragma unroll
            for (int r = 0; r < 4; r++) c[mt][nt][r] = 0.0f;

    for (int k0 = 0; k0 < DIM; k0 += BKT) {
        // A tile: x[row0..+127][k0..+31], coalesced float4, tf32-round, STS.128
#pragma unroll
        for (int i = 0; i < 4; i++) {
            const int id = t + i * 256;
            const int row = id >> 3, cg = id & 7;
            float4 v = make_float4(0.f, 0.f, 0.f, 0.f);
            const int gr = row0 + row;
            if (gr < NROWS) v = *(const float4*)&x[gr * DIM + k0 + cg * 4];
            uint4 u = make_uint4(f32_tf32(v.x), f32_tf32(v.y), f32_tf32(v.z), f32_tf32(v.w));
            *(uint4*)&As[row * ASTRIDE + cg * 4] = u;
        }
        // B tile: W[k0..+31][col0..+127]
#pragma unroll
        for (int i = 0; i < 4; i++) {
            const int id = t + i * 256;
            const int row = id >> 5, cg = id & 31;
            float4 v = *(const float4*)&B[(k0 + row) * DIM + col0 + cg * 4];
            uint4 u = make_uint4(f32_tf32(v.x), f32_tf32(v.y), f32_tf32(v.z), f32_tf32(v.w));
            *(uint4*)&Bs[row * BSTRIDE + cg * 4] = u;
        }
        __syncthreads();

#pragma unroll
        for (int ks = 0; ks < 4; ks++) {
            const int kb = ks * 8;
            uint32_t a[2][4];
#pragma unroll
            for (int mt = 0; mt < 2; mt++) {
                const int r0 = wm * 32 + mt * 16 + (l >> 2);
                a[mt][0] = As[r0 * ASTRIDE + kb + (l & 3)];
                a[mt][1] = As[(r0 + 8) * ASTRIDE + kb + (l & 3)];
                a[mt][2] = As[r0 * ASTRIDE + kb + (l & 3) + 4];
                a[mt][3] = As[(r0 + 8) * ASTRIDE + kb + (l & 3) + 4];
            }
#pragma unroll
            for (int nt = 0; nt < 8; nt++) {
                const int cn = wn * 64 + nt * 8 + (l >> 2);
                const uint32_t b0 = Bs[(kb + (l & 3)) * BSTRIDE + cn];
                const uint32_t b1 = Bs[(kb + (l & 3) + 4) * BSTRIDE + cn];
                mma_tf32(c[0][nt], a[0], b0, b1);
                mma_tf32(c[1][nt], a[1], b0, b1);
            }
        }
        __syncthreads();
    }

    // epilogue: bias (+relu), float2 stores
#pragma unroll
    for (int mt = 0; mt < 2; mt++) {
        const int gr0 = row0 + wm * 32 + mt * 16 + (l >> 2);
        const int gr1 = gr0 + 8;
#pragma unroll
        for (int nt = 0; nt < 8; nt++) {
            const int col = col0 + wn * 64 + nt * 8 + (l & 3) * 2;
            const float bb0 = bias[col], bb1 = bias[col + 1];
            float v0 = c[mt][nt][0] + bb0, v1 = c[mt][nt][1] + bb1;
            float v2 = c[mt][nt][2] + bb0, v3 = c[mt][nt][3] + bb1;
            if (relu) {
                v0 = fmaxf(v0, 0.f); v1 = fmaxf(v1, 0.f);
                v2 = fmaxf(v2, 0.f); v3 = fmaxf(v3, 0.f);
            }
            if (gr0 < NROWS) *(float2*)&C[gr0 * DIM + col] = make_float2(v0, v1);
            if (gr1 < NROWS) *(float2*)&C[gr1 * DIM + col] = make_float2(v2, v3);
        }
    }
}

// ---------------------------------------------------------------------------
// kv: KV[d][e] += sum_n K[n][d]*V[n][e]  (split-k, tensor-core TF32)
// grid: (4, KV_CHUNKS). x fastest: 4 tile positions of one chunk -> L2 reuse.
// Blocks with e-tile==0 also accumulate ksum (column sums of K) from smem.
// ---------------------------------------------------------------------------
__global__ __launch_bounds__(256, 2) void kv_kernel() {
    const int d0 = (blockIdx.x & 1) * BM;
    const int e0 = (blockIdx.x >> 1) * BN;
    const int n0 = blockIdx.y * KV_CHUNK;

    __shared__ uint32_t Ks[BKT * BSTRIDE];  // [32 n][128 d] stride 136
    __shared__ uint32_t Vs[BKT * BSTRIDE];  // [32 n][128 e] stride 136

    const int t = threadIdx.x;
    const int l = t & 31;
    const int w = t >> 5;
    const int wm = w >> 1, wn = w & 1;
    const bool do_ksum = (e0 == 0) && (t < 128);

    float c[2][8][4];
#pragma unroll
    for (int mt = 0; mt < 2; mt++)
#pragma unroll
        for (int nt = 0; nt < 8; nt++)
#pragma unroll
            for (int r = 0; r < 4; r++) c[mt][nt][r] = 0.0f;

    float ksacc = 0.0f;

    for (int n = n0; n < n0 + KV_CHUNK; n += BKT) {
#pragma unroll
        for (int i = 0; i < 4; i++) {
            const int id = t + i * 256;
            const int nn = id >> 5, dg = id & 31;
            const int gn = n + nn;
            float4 kf = make_float4(0.f, 0.f, 0.f, 0.f);
            float4 vf = make_float4(0.f, 0.f, 0.f, 0.f);
            if (gn < NROWS) {
                kf = *(const float4*)&g_K[gn * DIM + d0 + dg * 4];
                vf = *(const float4*)&g_V[gn * DIM + e0 + dg * 4];
            }
            *(uint4*)&Ks[nn * BSTRIDE + dg * 4] =
                make_uint4(f32_tf32(kf.x), f32_tf32(kf.y), f32_tf32(kf.z), f32_tf32(kf.w));
            *(uint4*)&Vs[nn * BSTRIDE + dg * 4] =
                make_uint4(f32_tf32(vf.x), f32_tf32(vf.y), f32_tf32(vf.z), f32_tf32(vf.w));
        }
        __syncthreads();

#pragma unroll
        for (int ks = 0; ks < 4; ks++) {
            const int kb = ks * 8;
            uint32_t a[2][4];
#pragma unroll
            for (int mt = 0; mt < 2; mt++) {
                const int dm = wm * 32 + mt * 16 + (l >> 2);
                a[mt][0] = Ks[(kb + (l & 3)) * BSTRIDE + dm];
                a[mt][1] = Ks[(kb + (l & 3)) * BSTRIDE + dm + 8];
                a[mt][2] = Ks[(kb + (l & 3) + 4) * BSTRIDE + dm];
                a[mt][3] = Ks[(kb + (l & 3) + 4) * BSTRIDE + dm + 8];
            }
#pragma unroll
            for (int nt = 0; nt < 8; nt++) {
                const int en = wn * 64 + nt * 8 + (l >> 2);
                const uint32_t b0 = Vs[(kb + (l & 3)) * BSTRIDE + en];
                const uint32_t b1 = Vs[(kb + (l & 3) + 4) * BSTRIDE + en];
                mma_tf32(c[0][nt], a[0], b0, b1);
                mma_tf32(c[1][nt], a[1], b0, b1);
            }
        }

        if (do_ksum) {
#pragma unroll
            for (int nn = 0; nn < BKT; nn++)
                ksacc += __uint_as_float(Ks[nn * BSTRIDE + t]);
        }
        __syncthreads();
    }

    if (do_ksum) atomicAdd(&g_ksum[d0 + t], ksacc);

#pragma unroll
    for (int mt = 0; mt < 2; mt++) {
        const int dr0 = d0 + wm * 32 + mt * 16 + (l >> 2);
#pragma unroll
        for (int nt = 0; nt < 8; nt++) {
            const int ec = e0 + wn * 64 + nt * 8 + (l & 3) * 2;
            atomicAdd(&g_KV[dr0 * DIM + ec],           c[mt][nt][0]);
            atomicAdd(&g_KV[dr0 * DIM + ec + 1],       c[mt][nt][1]);
            atomicAdd(&g_KV[(dr0 + 8) * DIM + ec],     c[mt][nt][2]);
            atomicAdd(&g_KV[(dr0 + 8) * DIM + ec + 1], c[mt][nt][3]);
        }
    }
}

// ---------------------------------------------------------------------------
// norm: g_norm[n] = dot(Q[n], ksum) + EPS   (warp per row, float4 loads)
// ---------------------------------------------------------------------------
__global__ void norm_kernel() {
    __shared__ float4 ks4[DIM / 4];
    const int t = threadIdx.x;
    if (t < DIM / 4) ks4[t] = *(const float4*)&g_ksum[t * 4];
    __syncthreads();

    const int lane = t & 31;
    const int gw = (blockIdx.x * blockDim.x + t) >> 5;
    const int nw = (gridDim.x * blockDim.x) >> 5;
    for (int row = gw; row < NROWS; row += nw) {
        const float4* q = (const float4*)&g_Q[row * DIM];
        const float4 a = q[lane], b = q[lane + 32];
        const float4 ka = ks4[lane], kb = ks4[lane + 32];
        float s = a.x * ka.x + a.y * ka.y + a.z * ka.z + a.w * ka.w
                + b.x * kb.x + b.y * kb.y + b.z * kb.z + b.w * kb.w;
#pragma unroll
        for (int o = 16; o; o >>= 1) s += __shfl_xor_sync(0xffffffffu, s, o);
        if (lane == 0) g_norm[row] = s + EPS;
    }
}

// ---------------------------------------------------------------------------
// out: out = (Q @ KV) / norm   (tensor-core TF32)   grid: (2, 782)
// ---------------------------------------------------------------------------
__global__ __launch_bounds__(256, 2) void out_kernel(float* __restrict__ out) {
    const int col0 = blockIdx.x * BN;
    const int row0 = blockIdx.y * BM;

    __shared__ uint32_t As[BM * ASTRIDE];
    __shared__ uint32_t Bs[BKT * BSTRIDE];

    const int t = threadIdx.x;
    const int l = t & 31;
    const int w = t >> 5;
    const int wm = w >> 1, wn = w & 1;

    float c[2][8][4];
#pragma unroll
    for (int mt = 0; mt < 2; mt++)
#pragma unroll
        for (int nt = 0; nt < 8; nt++)
#pragma unroll
            for (int r = 0; r < 4; r++) c[mt][nt][r] = 0.0f;

    for (int k0 = 0; k0 < DIM; k0 += BKT) {
#pragma unroll
        for (int i = 0; i < 4; i++) {
            const int id = t + i * 256;
            const int row = id >> 3, cg = id & 7;
            float4 v = make_float4(0.f, 0.f, 0.f, 0.f);
            const int gr = row0 + row;
            if (gr < NROWS) v = *(const float4*)&g_Q[gr * DIM + k0 + cg * 4];
            *(uint4*)&As[row * ASTRIDE + cg * 4] =
                make_uint4(f32_tf32(v.x), f32_tf32(v.y), f32_tf32(v.z), f32_tf32(v.w));
        }
#pragma unroll
        for (int i = 0; i < 4; i++) {
            const int id = t + i * 256;
            const int row = id >> 5, cg = id & 31;
            float4 v = *(const float4*)&g_KV[(k0 + row) * DIM + col0 + cg * 4];
            *(uint4*)&Bs[row * BSTRIDE + cg * 4] =
                make_uint4(f32_tf32(v.x), f32_tf32(v.y), f32_tf32(v.z), f32_tf32(v.w));
        }
        __syncthreads();

#pragma unroll
        for (int ks = 0; ks < 4; ks++) {
            const int kb = ks * 8;
            uint32_t a[2][4];
#pragma unroll
            for (int mt = 0; mt < 2; mt++) {
                const int r0 = wm * 32 + mt * 16 + (l >> 2);
                a[mt][0] = As[r0 * ASTRIDE + kb + (l & 3)];
                a[mt][1] = As[(r0 + 8) * ASTRIDE + kb + (l & 3)];
                a[mt][2] = As[r0 * ASTRIDE + kb + (l & 3) + 4];
                a[mt][3] = As[(r0 + 8) * ASTRIDE + kb + (l & 3) + 4];
            }
#pragma unroll
            for (int nt = 0; nt < 8; nt++) {
                const int cn = wn * 64 + nt * 8 + (l >> 2);
                const uint32_t b0 = Bs[(kb + (l & 3)) * BSTRIDE + cn];
                const uint32_t b1 = Bs[(kb + (l & 3) + 4) * BSTRIDE + cn];
                mma_tf32(c[0][nt], a[0], b0, b1);
                mma_tf32(c[1][nt], a[1], b0, b1);
            }
        }
        __syncthreads();
    }

#pragma unroll
    for (int mt = 0; mt < 2; mt++) {
        const int gr0 = row0 + wm * 32 + mt * 16 + (l >> 2);
        const int gr1 = gr0 + 8;
        const float inv0 = (gr0 < NROWS) ? 1.0f / g_norm[gr0] : 0.0f;
        const float inv1 = (gr1 < NROWS) ? 1.0f / g_norm[gr1] : 0.0f;
#pragma unroll
        for (int nt = 0; nt < 8; nt++) {
            const int col = col0 + wn * 64 + nt * 8 + (l & 3) * 2;
            if (gr0 < NROWS)
                *(float2*)&out[gr0 * DIM + col] =
                    make_float2(c[mt][nt][0] * inv0, c[mt][nt][1] * inv0);
            if (gr1 < NROWS)
                *(float2*)&out[gr1 * DIM + col] =
                    make_float2(c[mt][nt][2] * inv1, c[mt][nt][3] * inv1);
        }
    }
}

// ---------------------------------------------------------------------------
extern "C" void kernel_launch(void* const* d_in, const int* in_sizes, int n_in,
                              void* d_out, int out_size) {
    const float* x  = (const float*)d_in[0];
    const float* Wq = (const float*)d_in[1];
    const float* bq = (const float*)d_in[2];
    const float* Wk = (const float*)d_in[3];
    const float* bk = (const float*)d_in[4];
    const float* Wv = (const float*)d_in[5];
    const float* bv = (const float*)d_in[6];
    float* out = (float*)d_out;

    const int rowTiles = (NROWS + BM - 1) / BM;   // 782

    init_kernel<<<(DIM * DIM + 255) / 256, 256>>>();
    qkv_kernel<<<dim3(6, rowTiles), 256>>>(x, Wq, bq, Wk, bk, Wv, bv);
    kv_kernel<<<dim3(4, KV_CHUNKS), 256>>>();
    norm_kernel<<<592, 256>>>();
    out_kernel<<<dim3(2, rowTiles), 256>>>(out);
}

// round 8
// speedup vs baseline: 4.2421x; 1.4817x over previous
#include <cuda_runtime.h>
#include <cuda_fp16.h>
#include <cstdint>

#define NROWS 100000
#define NPAD  100096          // 782 * 128
#define DIM 256
#define EPS 1e-6f
#define KV_SCALE_INV 256.0f   // KVh = KV / 256

#define SA 40                 // A-tile row stride (halves), 128 rows x 32 k
#define SB 136                // B/K/V-tile row stride (halves), 32 rows x 128 cols
#define ABYTES (128 * SA * 2)
#define BBYTES (32 * SB * 2)

#define KV_NCHUNK 125
#define KV_TILES 25           // 25 tiles * 32 rows = 800 rows/chunk; 125*800 = 100000

// Scratch (allocation-guard-safe __device__ globals)
__device__ __half g_Q[NPAD * DIM];
__device__ __half g_K[NPAD * DIM];
__device__ __half g_V[NPAD * DIM];
__device__ __half g_Wh[3 * DIM * DIM];   // [z][k][n] fp16
__device__ float  g_KV[DIM * DIM];
__device__ __half g_KVh[DIM * DIM];      // KV / 256 as fp16, [d][e]
__device__ float  g_ksum[DIM];
__device__ float  g_norm[NROWS];

// ---------------------------------------------------------------------------
// PTX helpers
// ---------------------------------------------------------------------------
__device__ __forceinline__ uint32_t smem_u32(const void* p) {
    uint32_t a;
    asm("{ .reg .u64 t; cvta.to.shared.u64 t, %1; cvt.u32.u64 %0, t; }" : "=r"(a) : "l"(p));
    return a;
}

__device__ __forceinline__ void cp16(uint32_t dst, const void* src) {
    asm volatile("cp.async.cg.shared.global [%0], [%1], 16;" :: "r"(dst), "l"(src));
}
#define CP_COMMIT() asm volatile("cp.async.commit_group;" ::: "memory")
#define CP_WAIT(n)  asm volatile("cp.async.wait_group %0;" :: "n"(n) : "memory")

#define LDSM_X4(r, addr) \
    asm volatile("ldmatrix.sync.aligned.m8n8.x4.shared.b16 {%0,%1,%2,%3}, [%4];" \
                 : "=r"((r)[0]), "=r"((r)[1]), "=r"((r)[2]), "=r"((r)[3]) : "r"(addr))
#define LDSM_X4T(r, addr) \
    asm volatile("ldmatrix.sync.aligned.m8n8.x4.trans.shared.b16 {%0,%1,%2,%3}, [%4];" \
                 : "=r"((r)[0]), "=r"((r)[1]), "=r"((r)[2]), "=r"((r)[3]) : "r"(addr))

__device__ __forceinline__ void mma_fp16(float c[4], const uint32_t a[4],
                                         uint32_t b0, uint32_t b1) {
    asm volatile(
        "mma.sync.aligned.m16n8k16.row.col.f32.f16.f16.f32 "
        "{%0,%1,%2,%3},{%4,%5,%6,%7},{%8,%9},{%0,%1,%2,%3};\n"
        : "+f"(c[0]), "+f"(c[1]), "+f"(c[2]), "+f"(c[3])
        : "r"(a[0]), "r"(a[1]), "r"(a[2]), "r"(a[3]), "r"(b0), "r"(b1));
}

__device__ __forceinline__ uint32_t pack_h2(float a, float b) {
    __half2 h = __floats2half2_rn(a, b);
    return *reinterpret_cast<uint32_t*>(&h);
}

// ---------------------------------------------------------------------------
// prep: W -> fp16 [z][k][n]
// ---------------------------------------------------------------------------
__global__ void prep_w_kernel(const float* __restrict__ Wq,
                              const float* __restrict__ Wk,
                              const float* __restrict__ Wv) {
    const int z = blockIdx.y;
    const float* W = (z == 0) ? Wq : (z == 1) ? Wk : Wv;
    const int i = blockIdx.x * 256 + threadIdx.x;
    g_Wh[z * DIM * DIM + i] = __float2half_rn(W[i]);
}

// init: zero accumulators (every replay)
__global__ void init_kernel() {
    int t = blockIdx.x * blockDim.x + threadIdx.x;
    if (t < DIM * DIM) g_KV[t] = 0.0f;
    if (t < DIM)       g_ksum[t] = 0.0f;
}

// ---------------------------------------------------------------------------
// qkv: Q=relu(xWq+b), K=relu(xWk+b), V=xWv+b  -> fp16; ksum fused (z==1)
// grid (6, 782): x = z*2 + colhalf (fastest -> x-tile L2 reuse)
// ---------------------------------------------------------------------------
__global__ __launch_bounds__(256, 2) void qkv_kernel(
    const float* __restrict__ x,
    const float* __restrict__ bq, const float* __restrict__ bk,
    const float* __restrict__ bv)
{
    __shared__ __half Asm[2][128 * SA];
    __shared__ __half Bsm[2][32 * SB];
    __shared__ float colsum[128];

    const int t = threadIdx.x;
    const int l = t & 31, w = t >> 5;
    const int wm = w >> 1, wn = w & 1;

    const int zy = blockIdx.x;
    const int z = zy >> 1;
    const int col0 = (zy & 1) * 128;
    const int row0 = blockIdx.y * 128;

    const __half* Wh = g_Wh + z * DIM * DIM;
    const float* bias = (z == 0) ? bq : (z == 1) ? bk : bv;
    __half* C = (z == 0) ? g_Q : (z == 1) ? g_K : g_V;
    const bool relu = (z < 2);

    if (t < 128) colsum[t] = 0.0f;

    const uint32_t as_base = smem_u32(Asm);
    const uint32_t bs_base = smem_u32(Bsm);
    const int aoff = (l & 15) * SA + (l >> 4) * 8;
    const int boff = ((l & 7) + ((l >> 3) & 1) * 8) * SB + (l >> 4) * 8;

    float c[2][8][4];
#pragma unroll
    for (int mt = 0; mt < 2; mt++)
#pragma unroll
        for (int nt = 0; nt < 8; nt++)
#pragma unroll
            for (int r = 0; r < 4; r++) c[mt][nt][r] = 0.0f;

    float4 ar[4];

    auto loadA = [&](int kt) {
#pragma unroll
        for (int i = 0; i < 4; i++) {
            const int id = t + i * 256;
            const int row = id >> 3, c4 = (id & 7) * 4;
            const int gr = row0 + row;
            ar[i] = (gr < NROWS) ? *(const float4*)&x[gr * DIM + kt * 32 + c4]
                                 : make_float4(0.f, 0.f, 0.f, 0.f);
        }
    };
    auto stsA = [&](int kt) {
        __half* dst = Asm[kt & 1];
#pragma unroll
        for (int i = 0; i < 4; i++) {
            const int id = t + i * 256;
            const int row = id >> 3, c4 = (id & 7) * 4;
            uint2 u = make_uint2(pack_h2(ar[i].x, ar[i].y), pack_h2(ar[i].z, ar[i].w));
            *(uint2*)&dst[row * SA + c4] = u;
        }
    };
    auto cpB = [&](int kt) {
        const uint32_t dst = bs_base + (kt & 1) * BBYTES;
#pragma unroll
        for (int i = 0; i < 2; i++) {
            const int id = t + i * 256;
            const int row = id >> 4, cg = id & 15;
            cp16(dst + (row * SB + cg * 8) * 2,
                 &Wh[(kt * 32 + row) * DIM + col0 + cg * 8]);
        }
        CP_COMMIT();
    };
    auto compute = [&](int buf) {
        const uint32_t ab = as_base + buf * ABYTES;
        const uint32_t bb = bs_base + buf * BBYTES;
#pragma unroll
        for (int ks = 0; ks < 2; ks++) {
            uint32_t a[2][4];
#pragma unroll
            for (int mt = 0; mt < 2; mt++)
                LDSM_X4(a[mt], ab + 2 * ((wm * 32 + mt * 16) * SA + ks * 16 + aoff));
            uint32_t bqd[4][4];
#pragma unroll
            for (int nt2 = 0; nt2 < 4; nt2++)
                LDSM_X4T(bqd[nt2], bb + 2 * (ks * 16 * SB + wn * 64 + nt2 * 16 + boff));
#pragma unroll
            for (int mt = 0; mt < 2; mt++)
#pragma unroll
                for (int nt = 0; nt < 8; nt++) {
                    const int nt2 = nt >> 1, i0 = (nt & 1) * 2;
                    mma_fp16(c[mt][nt], a[mt], bqd[nt2][i0], bqd[nt2][i0 + 1]);
                }
        }
    };

    loadA(0); stsA(0); cpB(0);
#pragma unroll 1
    for (int kt = 0; kt < 8; kt++) {
        if (kt < 7) { loadA(kt + 1); cpB(kt + 1); }
        if (kt < 7) CP_WAIT(1); else CP_WAIT(0);
        __syncthreads();
        compute(kt & 1);
        __syncthreads();
        if (kt < 7) stsA(kt + 1);
    }

    // epilogue: bias (+relu), fp16 stores, ksum partials (z==1)
#pragma unroll
    for (int mt = 0; mt < 2; mt++) {
        const int gr0 = row0 + wm * 32 + mt * 16 + (l >> 2);
        const int gr1 = gr0 + 8;
#pragma unroll
        for (int nt = 0; nt < 8; nt++) {
            const int col = col0 + wn * 64 + nt * 8 + (l & 3) * 2;
            const float bb0 = bias[col], bb1 = bias[col + 1];
            float v0 = c[mt][nt][0] + bb0, v1 = c[mt][nt][1] + bb1;
            float v2 = c[mt][nt][2] + bb0, v3 = c[mt][nt][3] + bb1;
            if (relu) {
                v0 = fmaxf(v0, 0.f); v1 = fmaxf(v1, 0.f);
                v2 = fmaxf(v2, 0.f); v3 = fmaxf(v3, 0.f);
            }
            __half2 h01 = __floats2half2_rn(v0, v1);
            __half2 h23 = __floats2half2_rn(v2, v3);
            *(__half2*)&C[gr0 * DIM + col] = h01;   // padded arrays: always in-bounds
            *(__half2*)&C[gr1 * DIM + col] = h23;
            if (z == 1) {
                float s0 = (gr0 < NROWS ? v0 : 0.f) + (gr1 < NROWS ? v2 : 0.f);
                float s1 = (gr0 < NROWS ? v1 : 0.f) + (gr1 < NROWS ? v3 : 0.f);
                atomicAdd(&colsum[col - col0], s0);
                atomicAdd(&colsum[col - col0 + 1], s1);
            }
        }
    }
    if (z == 1) {
        __syncthreads();
        if (t < 128) atomicAdd(&g_ksum[col0 + t], colsum[t]);
    }
}

// ---------------------------------------------------------------------------
// kv: KV[d][e] += sum_n K[n][d] * V[n][e]   (fp16 mma, split-k, cp.async)
// grid (4, 125): x fastest -> chunk K/V tiles reused via L2
// ---------------------------------------------------------------------------
__global__ __launch_bounds__(256, 2) void kv_kernel() {
    __shared__ __half Ksm[2][32 * SB];
    __shared__ __half Vsm[2][32 * SB];

    const int t = threadIdx.x;
    const int l = t & 31, w = t >> 5;
    const int wm = w >> 1, wn = w & 1;

    const int d0 = (blockIdx.x & 1) * 128;
    const int e0 = (blockIdx.x >> 1) * 128;
    const int n0 = blockIdx.y * (KV_TILES * 32);

    const uint32_t kb_base = smem_u32(Ksm);
    const uint32_t vb_base = smem_u32(Vsm);
    const int kaoff = ((l & 7) + (l >> 4) * 8) * SB + ((l >> 3) & 1) * 8;
    const int boff  = ((l & 7) + ((l >> 3) & 1) * 8) * SB + (l >> 4) * 8;

    float c[2][8][4];
#pragma unroll
    for (int mt = 0; mt < 2; mt++)
#pragma unroll
        for (int nt = 0; nt < 8; nt++)
#pragma unroll
            for (int r = 0; r < 4; r++) c[mt][nt][r] = 0.0f;

    auto cpKV = [&](int kt) {
        const int buf = kt & 1;
        const uint32_t kd = kb_base + buf * BBYTES;
        const uint32_t vd = vb_base + buf * BBYTES;
        const int gn0 = n0 + kt * 32;
#pragma unroll
        for (int i = 0; i < 2; i++) {
            const int id = t + i * 256;
            const int row = id >> 4, cg = id & 15;
            cp16(kd + (row * SB + cg * 8) * 2, &g_K[(gn0 + row) * DIM + d0 + cg * 8]);
            cp16(vd + (row * SB + cg * 8) * 2, &g_V[(gn0 + row) * DIM + e0 + cg * 8]);
        }
        CP_COMMIT();
    };
    auto compute = [&](int buf) {
        const uint32_t kb = kb_base + buf * BBYTES;
        const uint32_t vb = vb_base + buf * BBYTES;
#pragma unroll
        for (int ks = 0; ks < 2; ks++) {
            uint32_t a[2][4];
#pragma unroll
            for (int mt = 0; mt < 2; mt++)
                LDSM_X4T(a[mt], kb + 2 * (ks * 16 * SB + wm * 32 + mt * 16 + kaoff));
            uint32_t bqd[4][4];
#pragma unroll
            for (int nt2 = 0; nt2 < 4; nt2++)
                LDSM_X4T(bqd[nt2], vb + 2 * (ks * 16 * SB + wn * 64 + nt2 * 16 + boff));
#pragma unroll
            for (int mt = 0; mt < 2; mt++)
#pragma unroll
                for (int nt = 0; nt < 8; nt++) {
                    const int nt2 = nt >> 1, i0 = (nt & 1) * 2;
                    mma_fp16(c[mt][nt], a[mt], bqd[nt2][i0], bqd[nt2][i0 + 1]);
                }
        }
    };

    cpKV(0);
#pragma unroll 1
    for (int kt = 0; kt < KV_TILES; kt++) {
        if (kt < KV_TILES - 1) cpKV(kt + 1);
        if (kt < KV_TILES - 1) CP_WAIT(1); else CP_WAIT(0);
        __syncthreads();
        compute(kt & 1);
        __syncthreads();
    }

#pragma unroll
    for (int mt = 0; mt < 2; mt++) {
        const int dr0 = d0 + wm * 32 + mt * 16 + (l >> 2);
#pragma unroll
        for (int nt = 0; nt < 8; nt++) {
            const int ec = e0 + wn * 64 + nt * 8 + (l & 3) * 2;
            atomicAdd(&g_KV[dr0 * DIM + ec],           c[mt][nt][0]);
            atomicAdd(&g_KV[dr0 * DIM + ec + 1],       c[mt][nt][1]);
            atomicAdd(&g_KV[(dr0 + 8) * DIM + ec],     c[mt][nt][2]);
            atomicAdd(&g_KV[(dr0 + 8) * DIM + ec + 1], c[mt][nt][3]);
        }
    }
}

// ---------------------------------------------------------------------------
// kvh: KVh = fp16(KV / 256)
// ---------------------------------------------------------------------------
__global__ void kvh_kernel() {
    const int i = blockIdx.x * 256 + threadIdx.x;
    g_KVh[i] = __float2half_rn(g_KV[i] * (1.0f / KV_SCALE_INV));
}

// ---------------------------------------------------------------------------
// norm: g_norm[n] = dot(Q[n], ksum) + EPS    (warp per row, fp16 Q)
// ---------------------------------------------------------------------------
__global__ void norm_kernel() {
    __shared__ float ks[DIM];
    const int t = threadIdx.x;
    if (t < DIM) ks[t] = g_ksum[t];
    __syncthreads();

    const int lane = t & 31;
    const int gw = (blockIdx.x * blockDim.x + t) >> 5;
    const int nw = (gridDim.x * blockDim.x) >> 5;
    for (int row = gw; row < NROWS; row += nw) {
        const uint4 raw = *(const uint4*)&g_Q[row * DIM + lane * 8];
        const __half2* h = (const __half2*)&raw;
        float s = 0.0f;
#pragma unroll
        for (int i = 0; i < 4; i++) {
            float2 f = __half22float2(h[i]);
            s += f.x * ks[lane * 8 + i * 2] + f.y * ks[lane * 8 + i * 2 + 1];
        }
#pragma unroll
        for (int o = 16; o; o >>= 1) s += __shfl_xor_sync(0xffffffffu, s, o);
        if (lane == 0) g_norm[row] = s + EPS;
    }
}

// ---------------------------------------------------------------------------
// out: out = (Q @ KVh) * 256 / norm      grid (2, 782)
// ---------------------------------------------------------------------------
__global__ __launch_bounds__(256, 2) void out_kernel(float* __restrict__ out) {
    __shared__ __half Asm[2][128 * SA];
    __shared__ __half Bsm[2][32 * SB];

    const int t = threadIdx.x;
    const int l = t & 31, w = t >> 5;
    const int wm = w >> 1, wn = w & 1;

    const int col0 = blockIdx.x * 128;
    const int row0 = blockIdx.y * 128;

    const uint32_t as_base = smem_u32(Asm);
    const uint32_t bs_base = smem_u32(Bsm);
    const int aoff = (l & 15) * SA + (l >> 4) * 8;
    const int boff = ((l & 7) + ((l >> 3) & 1) * 8) * SB + (l >> 4) * 8;

    float c[2][8][4];
#pragma unroll
    for (int mt = 0; mt < 2; mt++)
#pragma unroll
        for (int nt = 0; nt < 8; nt++)
#pragma unroll
            for (int r = 0; r < 4; r++) c[mt][nt][r] = 0.0f;

    auto cpA = [&](int kt) {
        const uint32_t dst = as_base + (kt & 1) * ABYTES;
#pragma unroll
        for (int i = 0; i < 2; i++) {
            const int id = t + i * 256;
            const int row = id >> 2, cg = id & 3;
            cp16(dst + (row * SA + cg * 8) * 2,
                 &g_Q[(row0 + row) * DIM + kt * 32 + cg * 8]);   // NPAD: in-bounds
        }
    };
    auto cpB = [&](int kt) {
        const uint32_t dst = bs_base + (kt & 1) * BBYTES;
#pragma unroll
        for (int i = 0; i < 2; i++) {
            const int id = t + i * 256;
            const int row = id >> 4, cg = id & 15;
            cp16(dst + (row * SB + cg * 8) * 2,
                 &g_KVh[(kt * 32 + row) * DIM + col0 + cg * 8]);
        }
    };
    auto compute = [&](int buf) {
        const uint32_t ab = as_base + buf * ABYTES;
        const uint32_t bb = bs_base + buf * BBYTES;
#pragma unroll
        for (int ks = 0; ks < 2; ks++) {
            uint32_t a[2][4];
#pragma unroll
            for (int mt = 0; mt < 2; mt++)
                LDSM_X4(a[mt], ab + 2 * ((wm * 32 + mt * 16) * SA + ks * 16 + aoff));
            uint32_t bqd[4][4];
#pragma unroll
            for (int nt2 = 0; nt2 < 4; nt2++)
                LDSM_X4T(bqd[nt2], bb + 2 * (ks * 16 * SB + wn * 64 + nt2 * 16 + boff));
#pragma unroll
            for (int mt = 0; mt < 2; mt++)
#pragma unroll
                for (int nt = 0; nt < 8; nt++) {
                    const int nt2 = nt >> 1, i0 = (nt & 1) * 2;
                    mma_fp16(c[mt][nt], a[mt], bqd[nt2][i0], bqd[nt2][i0 + 1]);
                }
        }
    };

    cpA(0); cpB(0); CP_COMMIT();
#pragma unroll 1
    for (int kt = 0; kt < 8; kt++) {
        if (kt < 7) { cpA(kt + 1); cpB(kt + 1); CP_COMMIT(); }
        if (kt < 7) CP_WAIT(1); else CP_WAIT(0);
        __syncthreads();
        compute(kt & 1);
        __syncthreads();
    }

#pragma unroll
    for (int mt = 0; mt < 2; mt++) {
        const int gr0 = row0 + wm * 32 + mt * 16 + (l >> 2);
        const int gr1 = gr0 + 8;
        const float inv0 = (gr0 < NROWS) ? KV_SCALE_INV / g_norm[gr0] : 0.0f;
        const float inv1 = (gr1 < NROWS) ? KV_SCALE_INV / g_norm[gr1] : 0.0f;
#pragma unroll
        for (int nt = 0; nt < 8; nt++) {
            const int col = col0 + wn * 64 + nt * 8 + (l & 3) * 2;
            if (gr0 < NROWS)
                *(float2*)&out[gr0 * DIM + col] =
                    make_float2(c[mt][nt][0] * inv0, c[mt][nt][1] * inv0);
            if (gr1 < NROWS)
                *(float2*)&out[gr1 * DIM + col] =
                    make_float2(c[mt][nt][2] * inv1, c[mt][nt][3] * inv1);
        }
    }
}

// ---------------------------------------------------------------------------
extern "C" void kernel_launch(void* const* d_in, const int* in_sizes, int n_in,
                              void* d_out, int out_size) {
    const float* x  = (const float*)d_in[0];
    const float* Wq = (const float*)d_in[1];
    const float* bq = (const float*)d_in[2];
    const float* Wk = (const float*)d_in[3];
    const float* bk = (const float*)d_in[4];
    const float* Wv = (const float*)d_in[5];
    const float* bv = (const float*)d_in[6];
    float* out = (float*)d_out;

    const int rowTiles = NPAD / 128;   // 782

    prep_w_kernel<<<dim3(DIM * DIM / 256, 3), 256>>>(Wq, Wk, Wv);
    init_kernel<<<(DIM * DIM + 255) / 256, 256>>>();
    qkv_kernel<<<dim3(6, rowTiles), 256>>>(x, bq, bk, bv);
    kv_kernel<<<dim3(4, KV_NCHUNK), 256>>>();
    kvh_kernel<<<DIM * DIM / 256, 256>>>();
    norm_kernel<<<1184, 256>>>();
    out_kernel<<<dim3(2, rowTiles), 256>>>(out);
}

// round 9
// speedup vs baseline: 4.2610x; 1.0045x over previous
#include <cuda_runtime.h>
#include <cuda_fp16.h>
#include <cstdint>

#define NROWS 100000
#define NPAD  100096          // 782 * 128
#define DIM 256
#define EPS 1e-6f
#define KV_SCALE_INV 256.0f   // KVh = KV / 256

#define SA 40                 // A-tile row stride (halves), 128 rows x 32 k
#define SB 136                // B/K/V-tile row stride (halves), 32 rows x 128 cols
#define ABYTES (128 * SA * 2)
#define BBYTES (32 * SB * 2)
#define STAGES 3

#define QKV_SMEM (STAGES * (ABYTES + BBYTES))   // 56832
#define OUT_SMEM (STAGES * (ABYTES + BBYTES))
#define KV_SMEM  (STAGES * 2 * BBYTES)          // 52224

#define KV_NCHUNK 125
#define KV_TILES 25           // 25*32 = 800 rows/chunk; 125*800 = 100000

// Scratch (allocation-guard-safe __device__ globals)
__device__ __half g_xh[NPAD * DIM];      // x as fp16 (pad rows stay zero-init)
__device__ __half g_Q[NPAD * DIM];
__device__ __half g_K[NPAD * DIM];
__device__ __half g_V[NPAD * DIM];
__device__ __half g_Wh[3 * DIM * DIM];   // [z][k][n] fp16
__device__ float  g_KV[DIM * DIM];
__device__ __half g_KVh[DIM * DIM];      // KV / 256 as fp16, [d][e]
__device__ float  g_ksum[DIM];
__device__ float  g_norm[NROWS];

// ---------------------------------------------------------------------------
// PTX helpers
// ---------------------------------------------------------------------------
__device__ __forceinline__ uint32_t smem_u32(const void* p) {
    uint32_t a;
    asm("{ .reg .u64 t; cvta.to.shared.u64 t, %1; cvt.u32.u64 %0, t; }" : "=r"(a) : "l"(p));
    return a;
}

__device__ __forceinline__ void cp16(uint32_t dst, const void* src) {
    asm volatile("cp.async.cg.shared.global [%0], [%1], 16;" :: "r"(dst), "l"(src));
}
#define CP_COMMIT() asm volatile("cp.async.commit_group;" ::: "memory")
#define CP_WAIT(n)  asm volatile("cp.async.wait_group %0;" :: "n"(n) : "memory")

#define LDSM_X4(r, addr) \
    asm volatile("ldmatrix.sync.aligned.m8n8.x4.shared.b16 {%0,%1,%2,%3}, [%4];" \
                 : "=r"((r)[0]), "=r"((r)[1]), "=r"((r)[2]), "=r"((r)[3]) : "r"(addr))
#define LDSM_X4T(r, addr) \
    asm volatile("ldmatrix.sync.aligned.m8n8.x4.trans.shared.b16 {%0,%1,%2,%3}, [%4];" \
                 : "=r"((r)[0]), "=r"((r)[1]), "=r"((r)[2]), "=r"((r)[3]) : "r"(addr))

__device__ __forceinline__ void mma_fp16(float c[4], const uint32_t a[4],
                                         uint32_t b0, uint32_t b1) {
    asm volatile(
        "mma.sync.aligned.m16n8k16.row.col.f32.f16.f16.f32 "
        "{%0,%1,%2,%3},{%4,%5,%6,%7},{%8,%9},{%0,%1,%2,%3};\n"
        : "+f"(c[0]), "+f"(c[1]), "+f"(c[2]), "+f"(c[3])
        : "r"(a[0]), "r"(a[1]), "r"(a[2]), "r"(a[3]), "r"(b0), "r"(b1));
}

__device__ __forceinline__ uint32_t pack_h2(float a, float b) {
    __half2 h = __floats2half2_rn(a, b);
    return *reinterpret_cast<uint32_t*>(&h);
}

// ---------------------------------------------------------------------------
// prep: x -> fp16 (g_xh) and W -> fp16 (g_Wh), one launch
// each thread converts 8 elements.  x groups: 3,200,000; W groups: 24,576
// grid = (3200000 + 24576) / 256 = 12596
// ---------------------------------------------------------------------------
__global__ void prep_kernel(const float* __restrict__ x,
                            const float* __restrict__ Wq,
                            const float* __restrict__ Wk,
                            const float* __restrict__ Wv) {
    const long id = (long)blockIdx.x * 256 + threadIdx.x;
    const long xgroups = (long)NROWS * DIM / 8;
    const float* src;
    __half* dst;
    long off;
    if (id < xgroups) {
        src = x; dst = g_xh; off = id * 8;
    } else {
        const long wi = id - xgroups;            // 0..24575
        const int z = (int)(wi >> 13);           // 8192 groups per matrix
        src = (z == 0) ? Wq : (z == 1) ? Wk : Wv;
        dst = g_Wh + z * DIM * DIM;
        off = (wi & 8191) * 8;
    }
    const float4 f0 = *(const float4*)&src[off];
    const float4 f1 = *(const float4*)&src[off + 4];
    uint4 u;
    u.x = pack_h2(f0.x, f0.y); u.y = pack_h2(f0.z, f0.w);
    u.z = pack_h2(f1.x, f1.y); u.w = pack_h2(f1.z, f1.w);
    *(uint4*)&dst[off] = u;
}

// init: zero accumulators (every replay)
__global__ void init_kernel() {
    int t = blockIdx.x * blockDim.x + threadIdx.x;
    if (t < DIM * DIM) g_KV[t] = 0.0f;
    if (t < DIM)       g_ksum[t] = 0.0f;
}

// ---------------------------------------------------------------------------
// qkv: Q=relu(xWq+b), K=relu(xWk+b), V=xWv+b  -> fp16; ksum fused (z==1)
// grid (6, 782): x = z*2 + colhalf (fastest -> x-tile L2 reuse)
// 3-stage cp.async pipeline, dynamic smem
// ---------------------------------------------------------------------------
__global__ __launch_bounds__(256, 2) void qkv_kernel(
    const float* __restrict__ bq, const float* __restrict__ bk,
    const float* __restrict__ bv)
{
    extern __shared__ char dsm[];
    __shared__ float colsum[128];

    const int t = threadIdx.x;
    const int l = t & 31, w = t >> 5;
    const int wm = w >> 1, wn = w & 1;

    const int zy = blockIdx.x;
    const int z = zy >> 1;
    const int col0 = (zy & 1) * 128;
    const int row0 = blockIdx.y * 128;

    const __half* Wh = g_Wh + z * DIM * DIM;
    const float* bias = (z == 0) ? bq : (z == 1) ? bk : bv;
    __half* C = (z == 0) ? g_Q : (z == 1) ? g_K : g_V;
    const bool relu = (z < 2);

    if (t < 128) colsum[t] = 0.0f;

    const uint32_t as_base = smem_u32(dsm);
    const uint32_t bs_base = as_base + STAGES * ABYTES;
    const int aoff = (l & 15) * SA + (l >> 4) * 8;
    const int boff = ((l & 7) + ((l >> 3) & 1) * 8) * SB + (l >> 4) * 8;

    float c[2][8][4];
#pragma unroll
    for (int mt = 0; mt < 2; mt++)
#pragma unroll
        for (int nt = 0; nt < 8; nt++)
#pragma unroll
            for (int r = 0; r < 4; r++) c[mt][nt][r] = 0.0f;

    auto cp = [&](int kt) {
        const int s = kt % STAGES;
        const uint32_t da = as_base + s * ABYTES;
#pragma unroll
        for (int i = 0; i < 2; i++) {
            const int id = t + i * 256;
            const int row = id >> 2, cg = id & 3;
            cp16(da + (row * SA + cg * 8) * 2,
                 &g_xh[(row0 + row) * DIM + kt * 32 + cg * 8]);
        }
        const uint32_t db = bs_base + s * BBYTES;
#pragma unroll
        for (int i = 0; i < 2; i++) {
            const int id = t + i * 256;
            const int row = id >> 4, cg = id & 15;
            cp16(db + (row * SB + cg * 8) * 2,
                 &Wh[(kt * 32 + row) * DIM + col0 + cg * 8]);
        }
        CP_COMMIT();
    };
    auto compute = [&](int s) {
        const uint32_t ab = as_base + s * ABYTES;
        const uint32_t bb = bs_base + s * BBYTES;
#pragma unroll
        for (int ks = 0; ks < 2; ks++) {
            uint32_t a[2][4];
#pragma unroll
            for (int mt = 0; mt < 2; mt++)
                LDSM_X4(a[mt], ab + 2 * ((wm * 32 + mt * 16) * SA + ks * 16 + aoff));
            uint32_t bqd[4][4];
#pragma unroll
            for (int nt2 = 0; nt2 < 4; nt2++)
                LDSM_X4T(bqd[nt2], bb + 2 * (ks * 16 * SB + wn * 64 + nt2 * 16 + boff));
#pragma unroll
            for (int mt = 0; mt < 2; mt++)
#pragma unroll
                for (int nt = 0; nt < 8; nt++) {
                    const int nt2 = nt >> 1, i0 = (nt & 1) * 2;
                    mma_fp16(c[mt][nt], a[mt], bqd[nt2][i0], bqd[nt2][i0 + 1]);
                }
        }
    };

    cp(0); cp(1);
#pragma unroll 1
    for (int kt = 0; kt < 8; kt++) {
        if (kt + 2 < 8) cp(kt + 2);
        if (kt < 6) CP_WAIT(2); else if (kt == 6) CP_WAIT(1); else CP_WAIT(0);
        __syncthreads();
        compute(kt % STAGES);
        __syncthreads();
    }

    // epilogue: bias (+relu), fp16 stores, ksum partials (z==1)
#pragma unroll
    for (int mt = 0; mt < 2; mt++) {
        const int gr0 = row0 + wm * 32 + mt * 16 + (l >> 2);
        const int gr1 = gr0 + 8;
#pragma unroll
        for (int nt = 0; nt < 8; nt++) {
            const int col = col0 + wn * 64 + nt * 8 + (l & 3) * 2;
            const float bb0 = bias[col], bb1 = bias[col + 1];
            float v0 = c[mt][nt][0] + bb0, v1 = c[mt][nt][1] + bb1;
            float v2 = c[mt][nt][2] + bb0, v3 = c[mt][nt][3] + bb1;
            if (relu) {
                v0 = fmaxf(v0, 0.f); v1 = fmaxf(v1, 0.f);
                v2 = fmaxf(v2, 0.f); v3 = fmaxf(v3, 0.f);
            }
            *(__half2*)&C[gr0 * DIM + col] = __floats2half2_rn(v0, v1);
            *(__half2*)&C[gr1 * DIM + col] = __floats2half2_rn(v2, v3);
            if (z == 1) {
                float s0 = (gr0 < NROWS ? v0 : 0.f) + (gr1 < NROWS ? v2 : 0.f);
                float s1 = (gr0 < NROWS ? v1 : 0.f) + (gr1 < NROWS ? v3 : 0.f);
                atomicAdd(&colsum[col - col0], s0);
                atomicAdd(&colsum[col - col0 + 1], s1);
            }
        }
    }
    if (z == 1) {
        __syncthreads();
        if (t < 128) atomicAdd(&g_ksum[col0 + t], colsum[t]);
    }
}

// ---------------------------------------------------------------------------
// kv: KV[d][e] += sum_n K[n][d] * V[n][e]   (fp16 mma, split-k, 3-stage)
// grid (4, 125): x fastest -> chunk K/V tiles reused via L2
// ---------------------------------------------------------------------------
__global__ __launch_bounds__(256, 2) void kv_kernel() {
    extern __shared__ char dsm[];

    const int t = threadIdx.x;
    const int l = t & 31, w = t >> 5;
    const int wm = w >> 1, wn = w & 1;

    const int d0 = (blockIdx.x & 1) * 128;
    const int e0 = (blockIdx.x >> 1) * 128;
    const int n0 = blockIdx.y * (KV_TILES * 32);

    const uint32_t kb_base = smem_u32(dsm);
    const uint32_t vb_base = kb_base + STAGES * BBYTES;
    const int kaoff = ((l & 7) + (l >> 4) * 8) * SB + ((l >> 3) & 1) * 8;
    const int boff  = ((l & 7) + ((l >> 3) & 1) * 8) * SB + (l >> 4) * 8;

    float c[2][8][4];
#pragma unroll
    for (int mt = 0; mt < 2; mt++)
#pragma unroll
        for (int nt = 0; nt < 8; nt++)
#pragma unroll
            for (int r = 0; r < 4; r++) c[mt][nt][r] = 0.0f;

    auto cp = [&](int kt) {
        const int s = kt % STAGES;
        const uint32_t kd = kb_base + s * BBYTES;
        const uint32_t vd = vb_base + s * BBYTES;
        const int gn0 = n0 + kt * 32;
#pragma unroll
        for (int i = 0; i < 2; i++) {
            const int id = t + i * 256;
            const int row = id >> 4, cg = id & 15;
            cp16(kd + (row * SB + cg * 8) * 2, &g_K[(gn0 + row) * DIM + d0 + cg * 8]);
            cp16(vd + (row * SB + cg * 8) * 2, &g_V[(gn0 + row) * DIM + e0 + cg * 8]);
        }
        CP_COMMIT();
    };
    auto compute = [&](int s) {
        const uint32_t kb = kb_base + s * BBYTES;
        const uint32_t vb = vb_base + s * BBYTES;
#pragma unroll
        for (int ks = 0; ks < 2; ks++) {
            uint32_t a[2][4];
#pragma unroll
            for (int mt = 0; mt < 2; mt++)
                LDSM_X4T(a[mt], kb + 2 * (ks * 16 * SB + wm * 32 + mt * 16 + kaoff));
            uint32_t bqd[4][4];
#pragma unroll
            for (int nt2 = 0; nt2 < 4; nt2++)
                LDSM_X4T(bqd[nt2], vb + 2 * (ks * 16 * SB + wn * 64 + nt2 * 16 + boff));
#pragma unroll
            for (int mt = 0; mt < 2; mt++)
#pragma unroll
                for (int nt = 0; nt < 8; nt++) {
                    const int nt2 = nt >> 1, i0 = (nt & 1) * 2;
                    mma_fp16(c[mt][nt], a[mt], bqd[nt2][i0], bqd[nt2][i0 + 1]);
                }
        }
    };

    cp(0); cp(1);
#pragma unroll 1
    for (int kt = 0; kt < KV_TILES; kt++) {
        if (kt + 2 < KV_TILES) cp(kt + 2);
        if (kt < KV_TILES - 2) CP_WAIT(2);
        else if (kt == KV_TILES - 2) CP_WAIT(1);
        else CP_WAIT(0);
        __syncthreads();
        compute(kt % STAGES);
        __syncthreads();
    }

#pragma unroll
    for (int mt = 0; mt < 2; mt++) {
        const int dr0 = d0 + wm * 32 + mt * 16 + (l >> 2);
#pragma unroll
        for (int nt = 0; nt < 8; nt++) {
            const int ec = e0 + wn * 64 + nt * 8 + (l & 3) * 2;
            atomicAdd(&g_KV[dr0 * DIM + ec],           c[mt][nt][0]);
            atomicAdd(&g_KV[dr0 * DIM + ec + 1],       c[mt][nt][1]);
            atomicAdd(&g_KV[(dr0 + 8) * DIM + ec],     c[mt][nt][2]);
            atomicAdd(&g_KV[(dr0 + 8) * DIM + ec + 1], c[mt][nt][3]);
        }
    }
}

// ---------------------------------------------------------------------------
// norm (+kvh fused): g_norm[n] = dot(Q[n], ksum) + EPS; blocks 0..63 also
// convert KV -> KVh.  2 rows per warp-iteration for MLP.
// ---------------------------------------------------------------------------
__global__ void norm_kernel() {
    if (blockIdx.x < 64) {
        const int i = (blockIdx.x * 256 + threadIdx.x) * 4;
        const float4 f = *(const float4*)&g_KV[i];
        const float s = 1.0f / KV_SCALE_INV;
        uint2 u;
        u.x = pack_h2(f.x * s, f.y * s);
        u.y = pack_h2(f.z * s, f.w * s);
        *(uint2*)&g_KVh[i] = u;
    }

    __shared__ float ks[DIM];
    const int t = threadIdx.x;
    if (t < DIM) ks[t] = g_ksum[t];
    __syncthreads();

    const int lane = t & 31;
    const int gw = (blockIdx.x * blockDim.x + t) >> 5;
    const int nw = (gridDim.x * blockDim.x) >> 5;
    for (int p = gw; p < NROWS / 2; p += nw) {
        const int r0 = p * 2, r1 = p * 2 + 1;
        const uint4 raw0 = *(const uint4*)&g_Q[r0 * DIM + lane * 8];
        const uint4 raw1 = *(const uint4*)&g_Q[r1 * DIM + lane * 8];
        const __half2* h0 = (const __half2*)&raw0;
        const __half2* h1 = (const __half2*)&raw1;
        float s0 = 0.0f, s1 = 0.0f;
#pragma unroll
        for (int i = 0; i < 4; i++) {
            const float k0 = ks[lane * 8 + i * 2], k1 = ks[lane * 8 + i * 2 + 1];
            float2 f0 = __half22float2(h0[i]);
            float2 f1 = __half22float2(h1[i]);
            s0 += f0.x * k0 + f0.y * k1;
            s1 += f1.x * k0 + f1.y * k1;
        }
#pragma unroll
        for (int o = 16; o; o >>= 1) {
            s0 += __shfl_xor_sync(0xffffffffu, s0, o);
            s1 += __shfl_xor_sync(0xffffffffu, s1, o);
        }
        if (lane == 0) { g_norm[r0] = s0 + EPS; g_norm[r1] = s1 + EPS; }
    }
}

// ---------------------------------------------------------------------------
// out: out = (Q @ KVh) * 256 / norm      grid (2, 782), 3-stage
// ---------------------------------------------------------------------------
__global__ __launch_bounds__(256, 2) void out_kernel(float* __restrict__ out) {
    extern __shared__ char dsm[];

    const int t = threadIdx.x;
    const int l = t & 31, w = t >> 5;
    const int wm = w >> 1, wn = w & 1;

    const int col0 = blockIdx.x * 128;
    const int row0 = blockIdx.y * 128;

    const uint32_t as_base = smem_u32(dsm);
    const uint32_t bs_base = as_base + STAGES * ABYTES;
    const int aoff = (l & 15) * SA + (l >> 4) * 8;
    const int boff = ((l & 7) + ((l >> 3) & 1) * 8) * SB + (l >> 4) * 8;

    float c[2][8][4];
#pragma unroll
    for (int mt = 0; mt < 2; mt++)
#pragma unroll
        for (int nt = 0; nt < 8; nt++)
#pragma unroll
            for (int r = 0; r < 4; r++) c[mt][nt][r] = 0.0f;

    auto cp = [&](int kt) {
        const int s = kt % STAGES;
        const uint32_t da = as_base + s * ABYTES;
#pragma unroll
        for (int i = 0; i < 2; i++) {
            const int id = t + i * 256;
            const int row = id >> 2, cg = id & 3;
            cp16(da + (row * SA + cg * 8) * 2,
                 &g_Q[(row0 + row) * DIM + kt * 32 + cg * 8]);
        }
        const uint32_t db = bs_base + s * BBYTES;
#pragma unroll
        for (int i = 0; i < 2; i++) {
            const int id = t + i * 256;
            const int row = id >> 4, cg = id & 15;
            cp16(db + (row * SB + cg * 8) * 2,
                 &g_KVh[(kt * 32 + row) * DIM + col0 + cg * 8]);
        }
        CP_COMMIT();
    };
    auto compute = [&](int s) {
        const uint32_t ab = as_base + s * ABYTES;
        const uint32_t bb = bs_base + s * BBYTES;
#pragma unroll
        for (int ks = 0; ks < 2; ks++) {
            uint32_t a[2][4];
#pragma unroll
            for (int mt = 0; mt < 2; mt++)
                LDSM_X4(a[mt], ab + 2 * ((wm * 32 + mt * 16) * SA + ks * 16 + aoff));
            uint32_t bqd[4][4];
#pragma unroll
            for (int nt2 = 0; nt2 < 4; nt2++)
                LDSM_X4T(bqd[nt2], bb + 2 * (ks * 16 * SB + wn * 64 + nt2 * 16 + boff));
#pragma unroll
            for (int mt = 0; mt < 2; mt++)
#pragma unroll
                for (int nt = 0; nt < 8; nt++) {
                    const int nt2 = nt >> 1, i0 = (nt & 1) * 2;
                    mma_fp16(c[mt][nt], a[mt], bqd[nt2][i0], bqd[nt2][i0 + 1]);
                }
        }
    };

    cp(0); cp(1);
#pragma unroll 1
    for (int kt = 0; kt < 8; kt++) {
        if (kt + 2 < 8) cp(kt + 2);
        if (kt < 6) CP_WAIT(2); else if (kt == 6) CP_WAIT(1); else CP_WAIT(0);
        __syncthreads();
        compute(kt % STAGES);
        __syncthreads();
    }

#pragma unroll
    for (int mt = 0; mt < 2; mt++) {
        const int gr0 = row0 + wm * 32 + mt * 16 + (l >> 2);
        const int gr1 = gr0 + 8;
        const float inv0 = (gr0 < NROWS) ? KV_SCALE_INV / g_norm[gr0] : 0.0f;
        const float inv1 = (gr1 < NROWS) ? KV_SCALE_INV / g_norm[gr1] : 0.0f;
#pragma unroll
        for (int nt = 0; nt < 8; nt++) {
            const int col = col0 + wn * 64 + nt * 8 + (l & 3) * 2;
            if (gr0 < NROWS)
                *(float2*)&out[gr0 * DIM + col] =
                    make_float2(c[mt][nt][0] * inv0, c[mt][nt][1] * inv0);
            if (gr1 < NROWS)
                *(float2*)&out[gr1 * DIM + col] =
                    make_float2(c[mt][nt][2] * inv1, c[mt][nt][3] * inv1);
        }
    }
}

// ---------------------------------------------------------------------------
extern "C" void kernel_launch(void* const* d_in, const int* in_sizes, int n_in,
                              void* d_out, int out_size) {
    const float* x  = (const float*)d_in[0];
    const float* Wq = (const float*)d_in[1];
    const float* bq = (const float*)d_in[2];
    const float* Wk = (const float*)d_in[3];
    const float* bk = (const float*)d_in[4];
    const float* Wv = (const float*)d_in[5];
    const float* bv = (const float*)d_in[6];
    float* out = (float*)d_out;

    cudaFuncSetAttribute(qkv_kernel, cudaFuncAttributeMaxDynamicSharedMemorySize, QKV_SMEM);
    cudaFuncSetAttribute(kv_kernel,  cudaFuncAttributeMaxDynamicSharedMemorySize, KV_SMEM);
    cudaFuncSetAttribute(out_kernel, cudaFuncAttributeMaxDynamicSharedMemorySize, OUT_SMEM);

    const int rowTiles = NPAD / 128;   // 782

    prep_kernel<<<12596, 256>>>(x, Wq, Wk, Wv);
    init_kernel<<<(DIM * DIM + 255) / 256, 256>>>();
    qkv_kernel<<<dim3(6, rowTiles), 256, QKV_SMEM>>>(bq, bk, bv);
    kv_kernel<<<dim3(4, KV_NCHUNK), 256, KV_SMEM>>>();
    norm_kernel<<<1184, 256>>>();
    out_kernel<<<dim3(2, rowTiles), 256, OUT_SMEM>>>(out);
}